// round 9
// baseline (speedup 1.0000x reference)
#include <cuda_runtime.h>
#include <cuda_fp16.h>
#include <cstdint>
#include <math.h>

// ---------------- problem constants ----------------
#define BB 8
#define NN 2048
#define FF 64
#define FHD 64
#define HH 4

#define TIx 64            // rows per CTA
#define TJx 64            // j per tile
#define NJT (NN / TJx)    // 32 j-tiles
#define THR2 256          // k_attn threads (8 warps)

#define ONES2 0x3C003C00u // half2(1.0, 1.0)

// ---------------- scratch ----------------
__device__ __half g_feats16[(size_t)BB * HH * NN * FHD]; // [b][h][n][o] fp16
__device__ float2 g_EG[BB * HH * NN];   // (exp(ss), exp(0.2 ss)) fp32
__device__ __half g_F16[BB * HH * NN];  // exp(sn) half
__device__ __half g_H16[BB * HH * NN];  // exp(0.2 sn) half
__device__ float  g_wa[2 * HH * FF];    // [which][h][f]
__device__ unsigned long long g_Abits[(size_t)BB * 32 * NN]; // [b][jt][i] 4MB

// ---------------- helpers ----------------
__device__ __forceinline__ uint32_t smem_u32(const void* p) {
    uint32_t a;
    asm("{ .reg .u64 t; cvta.to.shared.u64 t, %1; cvt.u32.u64 %0, t; }" : "=r"(a) : "l"(p));
    return a;
}
#define CP_ASYNC16(dst, src) \
    asm volatile("cp.async.cg.shared.global [%0], [%1], 16;" :: "r"(dst), "l"(src) : "memory")
#define CP_COMMIT() asm volatile("cp.async.commit_group;" ::: "memory")
#define CP_WAIT(n)  asm volatile("cp.async.wait_group %0;" :: "n"(n) : "memory")

__device__ __forceinline__ void ldmx4t(uint32_t* r, uint32_t addr) {
    asm volatile("ldmatrix.sync.aligned.m8n8.x4.trans.shared.b16 {%0,%1,%2,%3}, [%4];"
                 : "=r"(r[0]), "=r"(r[1]), "=r"(r[2]), "=r"(r[3]) : "r"(addr));
}
__device__ __forceinline__ void mma16816(float* c, const uint32_t* a, uint32_t b0, uint32_t b1) {
    asm volatile(
        "mma.sync.aligned.m16n8k16.row.col.f32.f16.f16.f32 "
        "{%0,%1,%2,%3},{%4,%5,%6,%7},{%8,%9},{%0,%1,%2,%3};"
        : "+f"(c[0]), "+f"(c[1]), "+f"(c[2]), "+f"(c[3])
        : "r"(a[0]), "r"(a[1]), "r"(a[2]), "r"(a[3]), "r"(b0), "r"(b1));
}
__device__ __forceinline__ uint32_t h2bits(__half2 v) {
    return *reinterpret_cast<uint32_t*>(&v);
}
__device__ __forceinline__ __half2 bits2h(uint32_t v) {
    return *reinterpret_cast<__half2*>(&v);
}

// ---------------- smem layout per stage (bytes) ----------------
// V: [4][64][72] half (144B pitch), F/H: [4][64] half, M: [64] uint64
#define OFF_V   0
#define OFF_F   36864
#define OFF_H   37376
#define OFF_M   37888
#define STGSZ   38400
#define NSTG    3
#define SMEM_SZ (NSTG * STGSZ)   // 115200/CTA -> 2 CTAs/SM (230400 <= 231424)

// ==================== Kernel 0: wa = W . a ====================
__global__ __launch_bounds__(256) void k_prep(
    const float* __restrict__ W, const float* __restrict__ a_self,
    const float* __restrict__ a_neigh) {
    const int lane = threadIdx.x & 31, wid = threadIdx.x >> 5;
    const int base = blockIdx.x * 32 + wid * 4;
#pragma unroll
    for (int u = 0; u < 4; ++u) {
        int idx = base + u;
        int which = idx >> 8, hf = idx & 255, h = hf >> 6;
        const float* ap = (which ? a_neigh : a_self) + h * 64;
        const float* wrow = W + (size_t)hf * 64;
        float s = wrow[lane] * ap[lane] + wrow[lane + 32] * ap[lane + 32];
#pragma unroll
        for (int d = 16; d > 0; d >>= 1) s += __shfl_xor_sync(0xffffffffu, s, d);
        if (lane == 0) g_wa[idx] = s;
    }
}

// ==================== Kernel P: pack A into bitmasks ====================
// block = 8 rows of one batch; warp w owns row i0+w; output [b][jt][i]
__global__ __launch_bounds__(256) void k_pack(const float* __restrict__ A) {
    __shared__ unsigned long long Wd[8][33];
    const int bx = blockIdx.x;
    const int b = bx >> 8, i0 = (bx & 255) * 8;
    const int t = threadIdx.x, lane = t & 31, wid = t >> 5;
    const float* row = A + ((size_t)(b * NN + i0 + wid)) * NN;
#pragma unroll 4
    for (int jt = 0; jt < 32; ++jt) {
        float v0 = row[jt * 64 + lane];
        float v1 = row[jt * 64 + 32 + lane];
        unsigned lo = __ballot_sync(0xffffffffu, v0 != 0.f);
        unsigned hi = __ballot_sync(0xffffffffu, v1 != 0.f);
        if (lane == 0) Wd[wid][jt] = ((unsigned long long)hi << 32) | lo;
    }
    __syncthreads();
    int jt = t >> 3, rl = t & 7;
    g_Abits[((size_t)(b * 32 + jt)) * NN + i0 + rl] = Wd[rl][jt];
}

// ==================== Kernel 1: feats (fp16) + E/G (fp32) + F/H (half) ====================
__global__ __launch_bounds__(256) void k_feats(
    const float* __restrict__ X, const float* __restrict__ W) {
    const int ROWS = 16;
    int bi = blockIdx.x;
    int b  = bi >> 7;
    int n0 = (bi & 127) * ROWS;
    int t = threadIdx.x;
    int h = t >> 6, o = t & 63;

    __shared__ float X_s[ROWS * 64];
    __shared__ __half F_s[ROWS][256];

    for (int idx = t; idx < ROWS * 64; idx += 256)
        X_s[idx] = X[(size_t)(b * NN + n0 + (idx >> 6)) * FF + (idx & 63)];

    float w_reg[64];
#pragma unroll
    for (int f = 0; f < 64; ++f) w_reg[f] = W[(h * 64 + f) * 64 + o];
    __syncthreads();

#pragma unroll
    for (int r = 0; r < ROWS; ++r) {
        float acc = 0.f;
#pragma unroll
        for (int f = 0; f < 64; ++f) acc += X_s[r * 64 + f] * w_reg[f];
        F_s[r][h * 64 + o] = __float2half(acc);
    }

    if (t < 128) {
        int r = t >> 3, hh = (t >> 1) & 3, wh = t & 1;
        const float* wap = g_wa + wh * 256 + hh * 64;
        float s = 0.f;
#pragma unroll
        for (int f = 0; f < 64; ++f) s += X_s[r * 64 + f] * wap[f];
        size_t idx = (size_t)(b * HH + hh) * NN + n0 + r;
        if (wh) {
            g_F16[idx] = __float2half_rn(__expf(s));
            g_H16[idx] = __float2half_rn(__expf(0.2f * s));
        } else {
            g_EG[idx] = make_float2(__expf(s), __expf(0.2f * s));
        }
    }
    __syncthreads();

#pragma unroll
    for (int k = 0; k < 2; ++k) {
        int e = t + k * 256;
        int r = e >> 5, c = (e & 31) * 8;
        int hh = c >> 6, o0 = c & 63;
        uint4 v = *reinterpret_cast<const uint4*>(&F_s[r][c]);
        *reinterpret_cast<uint4*>(
            &g_feats16[((size_t)(b * HH + hh) * NN + n0 + r) * FHD + o0]) = v;
    }
}

// ==================== Kernel 2: flash-GAT via mma.sync (bitmask A) ====================
extern __shared__ char smem[];

__global__ __launch_bounds__(THR2, 2) void k_attn(
    const float* __restrict__ bias, float* __restrict__ out) {
    const int b  = blockIdx.y;
    const int i0 = blockIdx.x * TIx;
    const int t = threadIdx.x, lane = t & 31, wid = t >> 5;
    const int h = wid >> 1;            // head
    const int rbase = (wid & 1) * 32;  // warp owns 32 rows
    const int g = lane >> 2;           // frag row group 0..7
    const int q = lane & 3;            // frag col group 0..3
    const uint32_t sb = smem_u32(smem);

    __shared__ uint32_t lutS[4];
    if (t < 4) {
        const uint32_t LUTC[4] = {0x00000000u, 0x00003C00u, 0x3C000000u, 0x3C003C00u};
        lutS[t] = LUTC[t];
    }

    auto issue_tile = [&](int jt, int stg) {
        const uint32_t base = sb + stg * STGSZ;
        const int j0 = jt * TJx;
#pragma unroll
        for (int k = 0; k < 8; ++k) {            // V: 4x64x64 half
            int e = t + k * 256;
            int hh = e >> 9, j = (e >> 3) & 63, o8 = e & 7;
            CP_ASYNC16(base + OFF_V + hh * 9216 + j * 144 + o8 * 16,
                       &g_feats16[((size_t)(b * HH + hh) * NN + j0 + j) * FHD + o8 * 8]);
        }
        if (t < 32) {                            // F: 4x64 half
            int hh = t >> 3, jj = (t & 7) * 8;
            CP_ASYNC16(base + OFF_F + hh * 128 + jj * 2,
                       &g_F16[(size_t)(b * HH + hh) * NN + j0 + jj]);
        } else if (t < 64) {                     // H: 4x64 half
            int t2 = t - 32;
            int hh = t2 >> 3, jj = (t2 & 7) * 8;
            CP_ASYNC16(base + OFF_H + hh * 128 + jj * 2,
                       &g_H16[(size_t)(b * HH + hh) * NN + j0 + jj]);
        } else if (t < 96) {                     // masks: 64 uint64 (512B)
            int idx = t - 64;
            CP_ASYNC16(base + OFF_M + idx * 16,
                       &g_Abits[((size_t)(b * 32 + jt)) * NN + i0 + idx * 2]);
        }
        CP_COMMIT();
    };

    // per-thread row constants as half2 duplicates (loop-invariant)
    __half2 E2d[2][2], G2d[2][2];
#pragma unroll
    for (int m = 0; m < 2; ++m)
#pragma unroll
        for (int hi = 0; hi < 2; ++hi) {
            float2 eg = g_EG[(size_t)(b * HH + h) * NN + i0 + rbase + m * 16 + g + hi * 8];
            E2d[m][hi] = __half2half2(__float2half_rn(eg.x));
            G2d[m][hi] = __half2half2(__float2half_rn(eg.y));
        }

    float acc[2][8][4];
#pragma unroll
    for (int m = 0; m < 2; ++m)
#pragma unroll
        for (int n = 0; n < 8; ++n)
#pragma unroll
            for (int c = 0; c < 4; ++c) acc[m][n][c] = 0.f;

    float acc_s[2][4];                 // row-sum accumulators (P @ ones)
#pragma unroll
    for (int m = 0; m < 2; ++m)
#pragma unroll
        for (int c = 0; c < 4; ++c) acc_s[m][c] = 0.f;

    issue_tile(0, 0);
    issue_tile(1, 1);

    const int rowlane = lane & 15, colsel = lane >> 4;

#pragma unroll 1
    for (int jt = 0; jt < NJT; ++jt) {
        const int stg = jt % NSTG;
        if (jt + 1 < NJT) CP_WAIT(1);
        else              CP_WAIT(0);
        __syncthreads();
        if (jt + 2 < NJT) issue_tile(jt + 2, (jt + 2) % NSTG);

        const char* sbase = smem + stg * STGSZ;
        const __half2* Fsh = (const __half2*)(sbase + OFF_F) + h * 32;
        const __half2* Hsh = (const __half2*)(sbase + OFF_H) + h * 32;
        const unsigned long long* Ms = (const unsigned long long*)(sbase + OFF_M);
        const uint32_t sbVh = sb + stg * STGSZ + OFF_V + h * 9216;

        // per-thread row masks, pre-shifted by q*2
        unsigned long long msk[2][2];
#pragma unroll
        for (int m = 0; m < 2; ++m)
#pragma unroll
            for (int hi = 0; hi < 2; ++hi)
                msk[m][hi] = Ms[rbase + m * 16 + g + hi * 8] >> (q * 2);

        // ---- build P in mma A-frag layout (half2 SIMD, bitmask gating) ----
        uint32_t afr[2][4][4];
#pragma unroll
        for (int k = 0; k < 4; ++k) {
            const int jc = k * 16 + q * 2;
            __half2 F2a = Fsh[jc >> 1], F2b = Fsh[(jc >> 1) + 4];
            __half2 H2a = Hsh[jc >> 1], H2b = Hsh[(jc >> 1) + 4];
#pragma unroll
            for (int m = 0; m < 2; ++m) {
                uint32_t slo0 = (uint32_t)(msk[m][0] >> (k * 16)) & 3u;
                uint32_t shi0 = (uint32_t)(msk[m][1] >> (k * 16)) & 3u;
                uint32_t slo8 = (uint32_t)(msk[m][0] >> (k * 16 + 8)) & 3u;
                uint32_t shi8 = (uint32_t)(msk[m][1] >> (k * 16 + 8)) & 3u;

                __half2 El = E2d[m][0], Gl = G2d[m][0];
                __half2 Eh = E2d[m][1], Gh = G2d[m][1];

                afr[m][k][0] = h2bits(__hmul2(
                    __hmax2(__hmul2(El, F2a), __hmul2(Gl, H2a)), bits2h(lutS[slo0])));
                afr[m][k][1] = h2bits(__hmul2(
                    __hmax2(__hmul2(Eh, F2a), __hmul2(Gh, H2a)), bits2h(lutS[shi0])));
                afr[m][k][2] = h2bits(__hmul2(
                    __hmax2(__hmul2(El, F2b), __hmul2(Gl, H2b)), bits2h(lutS[slo8])));
                afr[m][k][3] = h2bits(__hmul2(
                    __hmax2(__hmul2(Eh, F2b), __hmul2(Gh, H2b)), bits2h(lutS[shi8])));
            }
        }

        // ---- P @ V via HMMA, plus P @ ones for the denominator ----
#pragma unroll
        for (int n = 0; n < 4; ++n) {
#pragma unroll
            for (int k = 0; k < 4; ++k) {
                uint32_t bfr[4];
                ldmx4t(bfr, sbVh + (k * 16 + rowlane) * 144 + (n * 16 + colsel * 8) * 2);
#pragma unroll
                for (int m = 0; m < 2; ++m) {
                    mma16816(acc[m][2 * n],     afr[m][k], bfr[0], bfr[1]);
                    mma16816(acc[m][2 * n + 1], afr[m][k], bfr[2], bfr[3]);
                }
            }
        }
#pragma unroll
        for (int k = 0; k < 4; ++k)
#pragma unroll
            for (int m = 0; m < 2; ++m)
                mma16816(acc_s[m], afr[m][k], ONES2, ONES2);
        __syncthreads();
    }

    // ---- denominators: every lane already holds full row sums ----
    float inv[2][2];
#pragma unroll
    for (int m = 0; m < 2; ++m) {
        inv[m][0] = 1.f / acc_s[m][0];   // row rlo
        inv[m][1] = 1.f / acc_s[m][2];   // row rhi
    }

    // ---- epilogue: normalize + bias + relu ----
#pragma unroll
    for (int n = 0; n < 8; ++n) {
        const int col = h * 64 + n * 8 + q * 2;
        float2 bv = *reinterpret_cast<const float2*>(&bias[col]);
#pragma unroll
        for (int m = 0; m < 2; ++m) {
            const int rlo = i0 + rbase + m * 16 + g;
            float2 lo, hi2;
            lo.x  = fmaxf(acc[m][n][0] * inv[m][0] + bv.x, 0.f);
            lo.y  = fmaxf(acc[m][n][1] * inv[m][0] + bv.y, 0.f);
            hi2.x = fmaxf(acc[m][n][2] * inv[m][1] + bv.x, 0.f);
            hi2.y = fmaxf(acc[m][n][3] * inv[m][1] + bv.y, 0.f);
            *reinterpret_cast<float2*>(&out[((size_t)(b * NN + rlo)) * 256 + col]) = lo;
            *reinterpret_cast<float2*>(&out[((size_t)(b * NN + rlo + 8)) * 256 + col]) = hi2;
        }
    }
}

// ==================== launch ====================
extern "C" void kernel_launch(void* const* d_in, const int* in_sizes, int n_in,
                              void* d_out, int out_size) {
    const float* X       = (const float*)d_in[0];
    const float* A       = (const float*)d_in[1];
    const float* W       = (const float*)d_in[2];
    const float* bias    = (const float*)d_in[3];
    const float* a_self  = (const float*)d_in[4];
    const float* a_neigh = (const float*)d_in[5];
    float* out = (float*)d_out;

    static bool attr_set = false;
    if (!attr_set) {
        cudaFuncSetAttribute(k_attn, cudaFuncAttributeMaxDynamicSharedMemorySize, SMEM_SZ);
        attr_set = true;
    }

    k_prep<<<16, 256>>>(W, a_self, a_neigh);
    k_pack<<<BB * 256, 256>>>(A);
    k_feats<<<BB * NN / 16, 256>>>(X, W);
    dim3 grid2(NN / TIx, BB);
    k_attn<<<grid2, THR2, SMEM_SZ>>>(bias, out);
}

// round 10
// speedup vs baseline: 1.0840x; 1.0840x over previous
#include <cuda_runtime.h>
#include <cuda_fp16.h>
#include <cstdint>
#include <math.h>

// ---------------- problem constants ----------------
#define BB 8
#define NN 2048
#define FF 64
#define FHD 64
#define HH 4

#define TIx 128           // rows per CTA
#define TJx 64            // j per tile
#define NJT (NN / TJx)    // 32 j-tiles
#define THR2 512          // k_attn threads (16 warps)

#define ONES2 0x3C003C00u // half2(1.0, 1.0)

// ---------------- scratch ----------------
__device__ __half g_feats16[(size_t)BB * HH * NN * FHD]; // [b][h][n][o] fp16
__device__ float2 g_EG[BB * HH * NN];   // (exp(ss), exp(0.2 ss)) fp32
__device__ __half g_F16[BB * HH * NN];  // exp(sn) half
__device__ __half g_H16[BB * HH * NN];  // exp(0.2 sn) half
__device__ float  g_wa[2 * HH * FF];    // [which][h][f]
__device__ unsigned long long g_Abits[(size_t)BB * 32 * NN]; // [b][jt][i] 4MB

// ---------------- helpers ----------------
__device__ __forceinline__ uint32_t smem_u32(const void* p) {
    uint32_t a;
    asm("{ .reg .u64 t; cvta.to.shared.u64 t, %1; cvt.u32.u64 %0, t; }" : "=r"(a) : "l"(p));
    return a;
}
#define CP_ASYNC16(dst, src) \
    asm volatile("cp.async.cg.shared.global [%0], [%1], 16;" :: "r"(dst), "l"(src) : "memory")
#define CP_COMMIT() asm volatile("cp.async.commit_group;" ::: "memory")
#define CP_WAIT(n)  asm volatile("cp.async.wait_group %0;" :: "n"(n) : "memory")

__device__ __forceinline__ void ldmx4t(uint32_t* r, uint32_t addr) {
    asm volatile("ldmatrix.sync.aligned.m8n8.x4.trans.shared.b16 {%0,%1,%2,%3}, [%4];"
                 : "=r"(r[0]), "=r"(r[1]), "=r"(r[2]), "=r"(r[3]) : "r"(addr));
}
__device__ __forceinline__ void mma16816(float* c, const uint32_t* a, uint32_t b0, uint32_t b1) {
    asm volatile(
        "mma.sync.aligned.m16n8k16.row.col.f32.f16.f16.f32 "
        "{%0,%1,%2,%3},{%4,%5,%6,%7},{%8,%9},{%0,%1,%2,%3};"
        : "+f"(c[0]), "+f"(c[1]), "+f"(c[2]), "+f"(c[3])
        : "r"(a[0]), "r"(a[1]), "r"(a[2]), "r"(a[3]), "r"(b0), "r"(b1));
}
__device__ __forceinline__ uint32_t h2bits(__half2 v) {
    return *reinterpret_cast<uint32_t*>(&v);
}
__device__ __forceinline__ __half2 bits2h(uint32_t v) {
    return *reinterpret_cast<__half2*>(&v);
}

// ---------------- smem layout per stage (bytes) ----------------
// V: [4][64][72] half (144B pitch), F/H: [4][64] half, M: [128] uint64
#define OFF_V   0
#define OFF_F   36864
#define OFF_H   37376
#define OFF_M   37888
#define STGSZ   38912
#define NSTG    5
#define SMEM_SZ (NSTG * STGSZ)   // 194560/CTA -> 1 CTA/SM, deep ring

// ==================== Kernel 0: wa = W . a ====================
__global__ __launch_bounds__(256) void k_prep(
    const float* __restrict__ W, const float* __restrict__ a_self,
    const float* __restrict__ a_neigh) {
    const int lane = threadIdx.x & 31, wid = threadIdx.x >> 5;
    const int base = blockIdx.x * 32 + wid * 4;
#pragma unroll
    for (int u = 0; u < 4; ++u) {
        int idx = base + u;
        int which = idx >> 8, hf = idx & 255, h = hf >> 6;
        const float* ap = (which ? a_neigh : a_self) + h * 64;
        const float* wrow = W + (size_t)hf * 64;
        float s = wrow[lane] * ap[lane] + wrow[lane + 32] * ap[lane + 32];
#pragma unroll
        for (int d = 16; d > 0; d >>= 1) s += __shfl_xor_sync(0xffffffffu, s, d);
        if (lane == 0) g_wa[idx] = s;
    }
}

// ==================== Kernel P: pack A into bitmasks (MLP 16) ====================
__global__ __launch_bounds__(256) void k_pack(const float* __restrict__ A) {
    __shared__ unsigned long long Wd[8][33];
    const int bx = blockIdx.x;
    const int b = bx >> 8, i0 = (bx & 255) * 8;
    const int t = threadIdx.x, lane = t & 31, wid = t >> 5;
    const float* row = A + ((size_t)(b * NN + i0 + wid)) * NN;
#pragma unroll
    for (int grp = 0; grp < 4; ++grp) {
        float v0[8], v1[8];
#pragma unroll
        for (int u = 0; u < 8; ++u) {
            int jt = grp * 8 + u;
            v0[u] = row[jt * 64 + lane];
            v1[u] = row[jt * 64 + 32 + lane];
        }
#pragma unroll
        for (int u = 0; u < 8; ++u) {
            unsigned lo = __ballot_sync(0xffffffffu, v0[u] != 0.f);
            unsigned hi = __ballot_sync(0xffffffffu, v1[u] != 0.f);
            if (lane == 0) Wd[wid][grp * 8 + u] = ((unsigned long long)hi << 32) | lo;
        }
    }
    __syncthreads();
    int jt = t >> 3, rl = t & 7;
    g_Abits[((size_t)(b * 32 + jt)) * NN + i0 + rl] = Wd[rl][jt];
}

// ==================== Kernel 1: feats (fp16) + E/G (fp32) + F/H (half) ====================
__global__ __launch_bounds__(256) void k_feats(
    const float* __restrict__ X, const float* __restrict__ W) {
    const int ROWS = 16;
    int bi = blockIdx.x;
    int b  = bi >> 7;
    int n0 = (bi & 127) * ROWS;
    int t = threadIdx.x;
    int h = t >> 6, o = t & 63;

    __shared__ float X_s[ROWS * 64];
    __shared__ __half F_s[ROWS][256];

    for (int idx = t; idx < ROWS * 64; idx += 256)
        X_s[idx] = X[(size_t)(b * NN + n0 + (idx >> 6)) * FF + (idx & 63)];

    float w_reg[64];
#pragma unroll
    for (int f = 0; f < 64; ++f) w_reg[f] = W[(h * 64 + f) * 64 + o];
    __syncthreads();

#pragma unroll
    for (int r = 0; r < ROWS; ++r) {
        float acc = 0.f;
#pragma unroll
        for (int f = 0; f < 64; ++f) acc += X_s[r * 64 + f] * w_reg[f];
        F_s[r][h * 64 + o] = __float2half(acc);
    }

    if (t < 128) {
        int r = t >> 3, hh = (t >> 1) & 3, wh = t & 1;
        const float* wap = g_wa + wh * 256 + hh * 64;
        float s = 0.f;
#pragma unroll
        for (int f = 0; f < 64; ++f) s += X_s[r * 64 + f] * wap[f];
        size_t idx = (size_t)(b * HH + hh) * NN + n0 + r;
        if (wh) {
            g_F16[idx] = __float2half_rn(__expf(s));
            g_H16[idx] = __float2half_rn(__expf(0.2f * s));
        } else {
            g_EG[idx] = make_float2(__expf(s), __expf(0.2f * s));
        }
    }
    __syncthreads();

#pragma unroll
    for (int k = 0; k < 2; ++k) {
        int e = t + k * 256;
        int r = e >> 5, c = (e & 31) * 8;
        int hh = c >> 6, o0 = c & 63;
        uint4 v = *reinterpret_cast<const uint4*>(&F_s[r][c]);
        *reinterpret_cast<uint4*>(
            &g_feats16[((size_t)(b * HH + hh) * NN + n0 + r) * FHD + o0]) = v;
    }
}

// ==================== Kernel 2: flash-GAT (TIx=128, 5-stage ring) ====================
extern __shared__ char smem[];

__global__ __launch_bounds__(THR2, 1) void k_attn(
    const float* __restrict__ bias, float* __restrict__ out) {
    const int b  = blockIdx.y;
    const int i0 = blockIdx.x * TIx;
    const int t = threadIdx.x, lane = t & 31, wid = t >> 5;
    const int h = wid >> 2;            // head (4 warps per head)
    const int rbase = (wid & 3) * 32;  // warp owns 32 rows of 128
    const int g = lane >> 2;           // frag row group 0..7
    const int q = lane & 3;            // frag col group 0..3
    const uint32_t sb = smem_u32(smem);

    __shared__ uint32_t lutS[4];
    if (t < 4) {
        const uint32_t LUTC[4] = {0x00000000u, 0x00003C00u, 0x3C000000u, 0x3C003C00u};
        lutS[t] = LUTC[t];
    }

    auto issue_tile = [&](int jt, int stg) {
        if (jt < NJT) {
            const uint32_t base = sb + stg * STGSZ;
            const int j0 = jt * TJx;
#pragma unroll
            for (int k = 0; k < 4; ++k) {        // V: 4x64x64 half = 2048 uint4
                int e = t + k * THR2;
                int hh = e >> 9, j = (e >> 3) & 63, o8 = e & 7;
                CP_ASYNC16(base + OFF_V + hh * 9216 + j * 144 + o8 * 16,
                           &g_feats16[((size_t)(b * HH + hh) * NN + j0 + j) * FHD + o8 * 8]);
            }
            if (t < 32) {                        // F: 4x64 half
                int hh = t >> 3, jj = (t & 7) * 8;
                CP_ASYNC16(base + OFF_F + hh * 128 + jj * 2,
                           &g_F16[(size_t)(b * HH + hh) * NN + j0 + jj]);
            } else if (t < 64) {                 // H: 4x64 half
                int t2 = t - 32;
                int hh = t2 >> 3, jj = (t2 & 7) * 8;
                CP_ASYNC16(base + OFF_H + hh * 128 + jj * 2,
                           &g_H16[(size_t)(b * HH + hh) * NN + j0 + jj]);
            } else if (t < 128) {                // masks: 128 uint64 (1024B)
                int idx = t - 64;
                CP_ASYNC16(base + OFF_M + idx * 16,
                           &g_Abits[((size_t)(b * 32 + jt)) * NN + i0 + idx * 2]);
            }
        }
        CP_COMMIT();   // empty group when jt >= NJT keeps CP_WAIT count constant
    };

    // per-thread row constants as half2 duplicates (loop-invariant)
    __half2 E2d[2][2], G2d[2][2];
#pragma unroll
    for (int m = 0; m < 2; ++m)
#pragma unroll
        for (int hi = 0; hi < 2; ++hi) {
            float2 eg = g_EG[(size_t)(b * HH + h) * NN + i0 + rbase + m * 16 + g + hi * 8];
            E2d[m][hi] = __half2half2(__float2half_rn(eg.x));
            G2d[m][hi] = __half2half2(__float2half_rn(eg.y));
        }

    float acc[2][8][4];
#pragma unroll
    for (int m = 0; m < 2; ++m)
#pragma unroll
        for (int n = 0; n < 8; ++n)
#pragma unroll
            for (int c = 0; c < 4; ++c) acc[m][n][c] = 0.f;

    float acc_s[2][4];                 // row-sum accumulators (P @ ones)
#pragma unroll
    for (int m = 0; m < 2; ++m)
#pragma unroll
        for (int c = 0; c < 4; ++c) acc_s[m][c] = 0.f;

    issue_tile(0, 0);
    issue_tile(1, 1);
    issue_tile(2, 2);
    issue_tile(3, 3);

    const int rowlane = lane & 15, colsel = lane >> 4;

#pragma unroll 1
    for (int jt = 0; jt < NJT; ++jt) {
        const int stg = jt % NSTG;
        CP_WAIT(3);                      // stage jt complete (constant count)
        __syncthreads();
        issue_tile(jt + 4, (jt + 4) % NSTG);

        const char* sbase = smem + stg * STGSZ;
        const __half2* Fsh = (const __half2*)(sbase + OFF_F) + h * 32;
        const __half2* Hsh = (const __half2*)(sbase + OFF_H) + h * 32;
        const unsigned long long* Ms = (const unsigned long long*)(sbase + OFF_M);
        const uint32_t sbVh = sb + stg * STGSZ + OFF_V + h * 9216;

        // per-thread row masks, pre-shifted by q*2
        unsigned long long msk[2][2];
#pragma unroll
        for (int m = 0; m < 2; ++m)
#pragma unroll
            for (int hi = 0; hi < 2; ++hi)
                msk[m][hi] = Ms[rbase + m * 16 + g + hi * 8] >> (q * 2);

        // ---- build P in mma A-frag layout (half2 SIMD, bitmask gating) ----
        uint32_t afr[2][4][4];
#pragma unroll
        for (int k = 0; k < 4; ++k) {
            const int jc = k * 16 + q * 2;
            __half2 F2a = Fsh[jc >> 1], F2b = Fsh[(jc >> 1) + 4];
            __half2 H2a = Hsh[jc >> 1], H2b = Hsh[(jc >> 1) + 4];
#pragma unroll
            for (int m = 0; m < 2; ++m) {
                uint32_t slo0 = (uint32_t)(msk[m][0] >> (k * 16)) & 3u;
                uint32_t shi0 = (uint32_t)(msk[m][1] >> (k * 16)) & 3u;
                uint32_t slo8 = (uint32_t)(msk[m][0] >> (k * 16 + 8)) & 3u;
                uint32_t shi8 = (uint32_t)(msk[m][1] >> (k * 16 + 8)) & 3u;

                __half2 El = E2d[m][0], Gl = G2d[m][0];
                __half2 Eh = E2d[m][1], Gh = G2d[m][1];

                afr[m][k][0] = h2bits(__hmul2(
                    __hmax2(__hmul2(El, F2a), __hmul2(Gl, H2a)), bits2h(lutS[slo0])));
                afr[m][k][1] = h2bits(__hmul2(
                    __hmax2(__hmul2(Eh, F2a), __hmul2(Gh, H2a)), bits2h(lutS[shi0])));
                afr[m][k][2] = h2bits(__hmul2(
                    __hmax2(__hmul2(El, F2b), __hmul2(Gl, H2b)), bits2h(lutS[slo8])));
                afr[m][k][3] = h2bits(__hmul2(
                    __hmax2(__hmul2(Eh, F2b), __hmul2(Gh, H2b)), bits2h(lutS[shi8])));
            }
        }

        // ---- P @ V via HMMA, plus P @ ones for the denominator ----
#pragma unroll
        for (int n = 0; n < 4; ++n) {
#pragma unroll
            for (int k = 0; k < 4; ++k) {
                uint32_t bfr[4];
                ldmx4t(bfr, sbVh + (k * 16 + rowlane) * 144 + (n * 16 + colsel * 8) * 2);
#pragma unroll
                for (int m = 0; m < 2; ++m) {
                    mma16816(acc[m][2 * n],     afr[m][k], bfr[0], bfr[1]);
                    mma16816(acc[m][2 * n + 1], afr[m][k], bfr[2], bfr[3]);
                }
            }
        }
#pragma unroll
        for (int k = 0; k < 4; ++k)
#pragma unroll
            for (int m = 0; m < 2; ++m)
                mma16816(acc_s[m], afr[m][k], ONES2, ONES2);
        // no end-of-loop barrier: ring stages jt+4 never alias stages in use
    }

    // ---- denominators: every lane already holds full row sums ----
    float inv[2][2];
#pragma unroll
    for (int m = 0; m < 2; ++m) {
        inv[m][0] = 1.f / acc_s[m][0];   // row rlo
        inv[m][1] = 1.f / acc_s[m][2];   // row rhi
    }

    // ---- epilogue: normalize + bias + relu ----
#pragma unroll
    for (int n = 0; n < 8; ++n) {
        const int col = h * 64 + n * 8 + q * 2;
        float2 bv = *reinterpret_cast<const float2*>(&bias[col]);
#pragma unroll
        for (int m = 0; m < 2; ++m) {
            const int rlo = i0 + rbase + m * 16 + g;
            float2 lo, hi2;
            lo.x  = fmaxf(acc[m][n][0] * inv[m][0] + bv.x, 0.f);
            lo.y  = fmaxf(acc[m][n][1] * inv[m][0] + bv.y, 0.f);
            hi2.x = fmaxf(acc[m][n][2] * inv[m][1] + bv.x, 0.f);
            hi2.y = fmaxf(acc[m][n][3] * inv[m][1] + bv.y, 0.f);
            *reinterpret_cast<float2*>(&out[((size_t)(b * NN + rlo)) * 256 + col]) = lo;
            *reinterpret_cast<float2*>(&out[((size_t)(b * NN + rlo + 8)) * 256 + col]) = hi2;
        }
    }
}

// ==================== launch ====================
extern "C" void kernel_launch(void* const* d_in, const int* in_sizes, int n_in,
                              void* d_out, int out_size) {
    const float* X       = (const float*)d_in[0];
    const float* A       = (const float*)d_in[1];
    const float* W       = (const float*)d_in[2];
    const float* bias    = (const float*)d_in[3];
    const float* a_self  = (const float*)d_in[4];
    const float* a_neigh = (const float*)d_in[5];
    float* out = (float*)d_out;

    static bool attr_set = false;
    if (!attr_set) {
        cudaFuncSetAttribute(k_attn, cudaFuncAttributeMaxDynamicSharedMemorySize, SMEM_SZ);
        attr_set = true;
    }

    k_prep<<<16, 256>>>(W, a_self, a_neigh);
    k_pack<<<BB * 256, 256>>>(A);
    k_feats<<<BB * NN / 16, 256>>>(X, W);
    dim3 grid2(NN / TIx, BB);
    k_attn<<<grid2, THR2, SMEM_SZ>>>(bias, out);
}

// round 11
// speedup vs baseline: 1.1157x; 1.0293x over previous
#include <cuda_runtime.h>
#include <cuda_fp16.h>
#include <cstdint>
#include <math.h>

// ---------------- problem constants ----------------
#define BB 8
#define NN 2048
#define FF 64
#define FHD 64
#define HH 4

#define TIx 128           // rows per CTA
#define TJx 64            // j per tile
#define NJT (NN / TJx)    // 32 j-tiles
#define THR2 512          // k_attn threads (16 warps)

#define ONES2 0x3C003C00u // half2(1.0, 1.0)

// ---------------- scratch ----------------
__device__ __half g_feats16[(size_t)BB * HH * NN * FHD]; // [b][h][n][o] fp16
__device__ float2 g_EG[BB * HH * NN];   // (exp(ss), exp(0.2 ss)) fp32
__device__ __half g_F16[BB * HH * NN];  // exp(sn) half
__device__ __half g_H16[BB * HH * NN];  // exp(0.2 sn) half
__device__ float  g_wa[2 * HH * FF];    // [which][h][f]
__device__ unsigned long long g_Abits[(size_t)BB * 32 * NN]; // [b][jt][i] 4MB

// ---------------- helpers ----------------
__device__ __forceinline__ uint32_t smem_u32(const void* p) {
    uint32_t a;
    asm("{ .reg .u64 t; cvta.to.shared.u64 t, %1; cvt.u32.u64 %0, t; }" : "=r"(a) : "l"(p));
    return a;
}
#define CP_ASYNC16(dst, src) \
    asm volatile("cp.async.cg.shared.global [%0], [%1], 16;" :: "r"(dst), "l"(src) : "memory")
#define CP_COMMIT() asm volatile("cp.async.commit_group;" ::: "memory")
#define CP_WAIT(n)  asm volatile("cp.async.wait_group %0;" :: "n"(n) : "memory")

__device__ __forceinline__ void ldmx4t(uint32_t* r, uint32_t addr) {
    asm volatile("ldmatrix.sync.aligned.m8n8.x4.trans.shared.b16 {%0,%1,%2,%3}, [%4];"
                 : "=r"(r[0]), "=r"(r[1]), "=r"(r[2]), "=r"(r[3]) : "r"(addr));
}
__device__ __forceinline__ void mma16816(float* c, const uint32_t* a, uint32_t b0, uint32_t b1) {
    asm volatile(
        "mma.sync.aligned.m16n8k16.row.col.f32.f16.f16.f32 "
        "{%0,%1,%2,%3},{%4,%5,%6,%7},{%8,%9},{%0,%1,%2,%3};"
        : "+f"(c[0]), "+f"(c[1]), "+f"(c[2]), "+f"(c[3])
        : "r"(a[0]), "r"(a[1]), "r"(a[2]), "r"(a[3]), "r"(b0), "r"(b1));
}
__device__ __forceinline__ uint32_t h2bits(__half2 v) {
    return *reinterpret_cast<uint32_t*>(&v);
}
__device__ __forceinline__ __half2 bits2h(uint32_t v) {
    return *reinterpret_cast<__half2*>(&v);
}

// ---------------- smem layout per stage (bytes) ----------------
#define OFF_V   0
#define OFF_F   36864
#define OFF_H   37376
#define OFF_M   37888
#define STGSZ   38912
#define NSTG    5
#define SMEM_SZ (NSTG * STGSZ)   // 194560/CTA -> 1 CTA/SM, deep ring

// ==================== Kernel 0: wa = W . a ====================
__global__ __launch_bounds__(256) void k_prep(
    const float* __restrict__ W, const float* __restrict__ a_self,
    const float* __restrict__ a_neigh) {
    const int lane = threadIdx.x & 31, wid = threadIdx.x >> 5;
    const int base = blockIdx.x * 32 + wid * 4;
#pragma unroll
    for (int u = 0; u < 4; ++u) {
        int idx = base + u;
        int which = idx >> 8, hf = idx & 255, h = hf >> 6;
        const float* ap = (which ? a_neigh : a_self) + h * 64;
        const float* wrow = W + (size_t)hf * 64;
        float s = wrow[lane] * ap[lane] + wrow[lane + 32] * ap[lane + 32];
#pragma unroll
        for (int d = 16; d > 0; d >>= 1) s += __shfl_xor_sync(0xffffffffu, s, d);
        if (lane == 0) g_wa[idx] = s;
    }
}

// ==================== Fused kernel: A-pack (blocks 0..2047) + feats (2048..3071) ====================
__global__ __launch_bounds__(256) void k_fused(
    const float* __restrict__ A, const float* __restrict__ X,
    const float* __restrict__ W) {
    const int t = threadIdx.x;

    if (blockIdx.x < 2048) {
        // ---------------- pack A into bitmasks (MLP 16) ----------------
        __shared__ unsigned long long Wd[8][33];
        const int bx = blockIdx.x;
        const int b = bx >> 8, i0 = (bx & 255) * 8;
        const int lane = t & 31, wid = t >> 5;
        const float* row = A + ((size_t)(b * NN + i0 + wid)) * NN;
#pragma unroll
        for (int grp = 0; grp < 4; ++grp) {
            float v0[8], v1[8];
#pragma unroll
            for (int u = 0; u < 8; ++u) {
                int jt = grp * 8 + u;
                v0[u] = row[jt * 64 + lane];
                v1[u] = row[jt * 64 + 32 + lane];
            }
#pragma unroll
            for (int u = 0; u < 8; ++u) {
                unsigned lo = __ballot_sync(0xffffffffu, v0[u] != 0.f);
                unsigned hi = __ballot_sync(0xffffffffu, v1[u] != 0.f);
                if (lane == 0) Wd[wid][grp * 8 + u] = ((unsigned long long)hi << 32) | lo;
            }
        }
        __syncthreads();
        int jt = t >> 3, rl = t & 7;
        g_Abits[((size_t)(b * 32 + jt)) * NN + i0 + rl] = Wd[rl][jt];
    } else {
        // ---------------- feats (fp16) + E/G (fp32) + F/H (half) ----------------
        const int ROWS = 16;
        int bi = blockIdx.x - 2048;
        int b  = bi >> 7;
        int n0 = (bi & 127) * ROWS;
        int h = t >> 6, o = t & 63;

        __shared__ float X_s[ROWS * 64];
        __shared__ __half F_s[ROWS][256];

        for (int idx = t; idx < ROWS * 64; idx += 256)
            X_s[idx] = X[(size_t)(b * NN + n0 + (idx >> 6)) * FF + (idx & 63)];

        float w_reg[64];
#pragma unroll
        for (int f = 0; f < 64; ++f) w_reg[f] = W[(h * 64 + f) * 64 + o];
        __syncthreads();

#pragma unroll
        for (int r = 0; r < ROWS; ++r) {
            float acc = 0.f;
#pragma unroll
            for (int f = 0; f < 64; ++f) acc += X_s[r * 64 + f] * w_reg[f];
            F_s[r][h * 64 + o] = __float2half(acc);
        }

        if (t < 128) {
            int r = t >> 3, hh = (t >> 1) & 3, wh = t & 1;
            const float* wap = g_wa + wh * 256 + hh * 64;
            float s = 0.f;
#pragma unroll
            for (int f = 0; f < 64; ++f) s += X_s[r * 64 + f] * wap[f];
            size_t idx = (size_t)(b * HH + hh) * NN + n0 + r;
            if (wh) {
                g_F16[idx] = __float2half_rn(__expf(s));
                g_H16[idx] = __float2half_rn(__expf(0.2f * s));
            } else {
                g_EG[idx] = make_float2(__expf(s), __expf(0.2f * s));
            }
        }
        __syncthreads();

#pragma unroll
        for (int k = 0; k < 2; ++k) {
            int e = t + k * 256;
            int r = e >> 5, c = (e & 31) * 8;
            int hh = c >> 6, o0 = c & 63;
            uint4 v = *reinterpret_cast<const uint4*>(&F_s[r][c]);
            *reinterpret_cast<uint4*>(
                &g_feats16[((size_t)(b * HH + hh) * NN + n0 + r) * FHD + o0]) = v;
        }
    }
}

// ==================== Kernel 2: flash-GAT (TIx=128, 5-stage ring) ====================
extern __shared__ char smem[];

__global__ __launch_bounds__(THR2, 1) void k_attn(
    const float* __restrict__ bias, float* __restrict__ out) {
    const int b  = blockIdx.y;
    const int i0 = blockIdx.x * TIx;
    const int t = threadIdx.x, lane = t & 31, wid = t >> 5;
    const int h = wid >> 2;            // head (4 warps per head)
    const int rbase = (wid & 3) * 32;  // warp owns 32 rows of 128
    const int g = lane >> 2;           // frag row group 0..7
    const int q = lane & 3;            // frag col group 0..3
    const uint32_t sb = smem_u32(smem);

    __shared__ uint32_t lutS[4];
    if (t < 4) {
        const uint32_t LUTC[4] = {0x00000000u, 0x00003C00u, 0x3C000000u, 0x3C003C00u};
        lutS[t] = LUTC[t];
    }

    auto issue_tile = [&](int jt, int stg) {
        if (jt < NJT) {
            const uint32_t base = sb + stg * STGSZ;
            const int j0 = jt * TJx;
#pragma unroll
            for (int k = 0; k < 4; ++k) {        // V: 4x64x64 half = 2048 uint4
                int e = t + k * THR2;
                int hh = e >> 9, j = (e >> 3) & 63, o8 = e & 7;
                CP_ASYNC16(base + OFF_V + hh * 9216 + j * 144 + o8 * 16,
                           &g_feats16[((size_t)(b * HH + hh) * NN + j0 + j) * FHD + o8 * 8]);
            }
            if (t < 32) {                        // F: 4x64 half
                int hh = t >> 3, jj = (t & 7) * 8;
                CP_ASYNC16(base + OFF_F + hh * 128 + jj * 2,
                           &g_F16[(size_t)(b * HH + hh) * NN + j0 + jj]);
            } else if (t < 64) {                 // H: 4x64 half
                int t2 = t - 32;
                int hh = t2 >> 3, jj = (t2 & 7) * 8;
                CP_ASYNC16(base + OFF_H + hh * 128 + jj * 2,
                           &g_H16[(size_t)(b * HH + hh) * NN + j0 + jj]);
            } else if (t < 128) {                // masks: 128 uint64 (1024B)
                int idx = t - 64;
                CP_ASYNC16(base + OFF_M + idx * 16,
                           &g_Abits[((size_t)(b * 32 + jt)) * NN + i0 + idx * 2]);
            }
        }
        CP_COMMIT();   // empty group when jt >= NJT keeps CP_WAIT count constant
    };

    // per-thread row constants as half2 duplicates (loop-invariant)
    __half2 E2d[2][2], G2d[2][2];
#pragma unroll
    for (int m = 0; m < 2; ++m)
#pragma unroll
        for (int hi = 0; hi < 2; ++hi) {
            float2 eg = g_EG[(size_t)(b * HH + h) * NN + i0 + rbase + m * 16 + g + hi * 8];
            E2d[m][hi] = __half2half2(__float2half_rn(eg.x));
            G2d[m][hi] = __half2half2(__float2half_rn(eg.y));
        }

    float acc[2][8][4];
#pragma unroll
    for (int m = 0; m < 2; ++m)
#pragma unroll
        for (int n = 0; n < 8; ++n)
#pragma unroll
            for (int c = 0; c < 4; ++c) acc[m][n][c] = 0.f;

    float acc_s[2][4];                 // row-sum accumulators (P @ ones)
#pragma unroll
    for (int m = 0; m < 2; ++m)
#pragma unroll
        for (int c = 0; c < 4; ++c) acc_s[m][c] = 0.f;

    issue_tile(0, 0);
    issue_tile(1, 1);
    issue_tile(2, 2);
    issue_tile(3, 3);

    const int rowlane = lane & 15, colsel = lane >> 4;

#pragma unroll 1
    for (int jt = 0; jt < NJT; ++jt) {
        const int stg = jt % NSTG;
        CP_WAIT(3);                      // stage jt complete (constant count)
        __syncthreads();
        issue_tile(jt + 4, (jt + 4) % NSTG);

        const char* sbase = smem + stg * STGSZ;
        const __half2* Fsh = (const __half2*)(sbase + OFF_F) + h * 32;
        const __half2* Hsh = (const __half2*)(sbase + OFF_H) + h * 32;
        const unsigned long long* Ms = (const unsigned long long*)(sbase + OFF_M);
        const uint32_t sbVh = sb + stg * STGSZ + OFF_V + h * 9216;

        // per-thread row masks, pre-shifted by q*2
        unsigned long long msk[2][2];
#pragma unroll
        for (int m = 0; m < 2; ++m)
#pragma unroll
            for (int hi = 0; hi < 2; ++hi)
                msk[m][hi] = Ms[rbase + m * 16 + g + hi * 8] >> (q * 2);

        // ---- build P in mma A-frag layout (half2 SIMD, bitmask gating) ----
        uint32_t afr[2][4][4];
#pragma unroll
        for (int k = 0; k < 4; ++k) {
            const int jc = k * 16 + q * 2;
            __half2 F2a = Fsh[jc >> 1], F2b = Fsh[(jc >> 1) + 4];
            __half2 H2a = Hsh[jc >> 1], H2b = Hsh[(jc >> 1) + 4];
#pragma unroll
            for (int m = 0; m < 2; ++m) {
                uint32_t slo0 = (uint32_t)(msk[m][0] >> (k * 16)) & 3u;
                uint32_t shi0 = (uint32_t)(msk[m][1] >> (k * 16)) & 3u;
                uint32_t slo8 = (uint32_t)(msk[m][0] >> (k * 16 + 8)) & 3u;
                uint32_t shi8 = (uint32_t)(msk[m][1] >> (k * 16 + 8)) & 3u;

                __half2 El = E2d[m][0], Gl = G2d[m][0];
                __half2 Eh = E2d[m][1], Gh = G2d[m][1];

                afr[m][k][0] = h2bits(__hmul2(
                    __hmax2(__hmul2(El, F2a), __hmul2(Gl, H2a)), bits2h(lutS[slo0])));
                afr[m][k][1] = h2bits(__hmul2(
                    __hmax2(__hmul2(Eh, F2a), __hmul2(Gh, H2a)), bits2h(lutS[shi0])));
                afr[m][k][2] = h2bits(__hmul2(
                    __hmax2(__hmul2(El, F2b), __hmul2(Gl, H2b)), bits2h(lutS[slo8])));
                afr[m][k][3] = h2bits(__hmul2(
                    __hmax2(__hmul2(Eh, F2b), __hmul2(Gh, H2b)), bits2h(lutS[shi8])));
            }
        }

        // ---- P @ V via HMMA, plus P @ ones for the denominator ----
#pragma unroll
        for (int n = 0; n < 4; ++n) {
#pragma unroll
            for (int k = 0; k < 4; ++k) {
                uint32_t bfr[4];
                ldmx4t(bfr, sbVh + (k * 16 + rowlane) * 144 + (n * 16 + colsel * 8) * 2);
#pragma unroll
                for (int m = 0; m < 2; ++m) {
                    mma16816(acc[m][2 * n],     afr[m][k], bfr[0], bfr[1]);
                    mma16816(acc[m][2 * n + 1], afr[m][k], bfr[2], bfr[3]);
                }
            }
        }
#pragma unroll
        for (int k = 0; k < 4; ++k)
#pragma unroll
            for (int m = 0; m < 2; ++m)
                mma16816(acc_s[m], afr[m][k], ONES2, ONES2);
        // no end-of-loop barrier: ring stages jt+4 never alias stages in use
    }

    // ---- denominators: every lane already holds full row sums ----
    float inv[2][2];
#pragma unroll
    for (int m = 0; m < 2; ++m) {
        inv[m][0] = 1.f / acc_s[m][0];   // row rlo
        inv[m][1] = 1.f / acc_s[m][2];   // row rhi
    }

    // ---- epilogue: normalize + bias + relu ----
#pragma unroll
    for (int n = 0; n < 8; ++n) {
        const int col = h * 64 + n * 8 + q * 2;
        float2 bv = *reinterpret_cast<const float2*>(&bias[col]);
#pragma unroll
        for (int m = 0; m < 2; ++m) {
            const int rlo = i0 + rbase + m * 16 + g;
            float2 lo, hi2;
            lo.x  = fmaxf(acc[m][n][0] * inv[m][0] + bv.x, 0.f);
            lo.y  = fmaxf(acc[m][n][1] * inv[m][0] + bv.y, 0.f);
            hi2.x = fmaxf(acc[m][n][2] * inv[m][1] + bv.x, 0.f);
            hi2.y = fmaxf(acc[m][n][3] * inv[m][1] + bv.y, 0.f);
            *reinterpret_cast<float2*>(&out[((size_t)(b * NN + rlo)) * 256 + col]) = lo;
            *reinterpret_cast<float2*>(&out[((size_t)(b * NN + rlo + 8)) * 256 + col]) = hi2;
        }
    }
}

// ==================== launch ====================
extern "C" void kernel_launch(void* const* d_in, const int* in_sizes, int n_in,
                              void* d_out, int out_size) {
    const float* X       = (const float*)d_in[0];
    const float* A       = (const float*)d_in[1];
    const float* W       = (const float*)d_in[2];
    const float* bias    = (const float*)d_in[3];
    const float* a_self  = (const float*)d_in[4];
    const float* a_neigh = (const float*)d_in[5];
    float* out = (float*)d_out;

    static bool attr_set = false;
    if (!attr_set) {
        cudaFuncSetAttribute(k_attn, cudaFuncAttributeMaxDynamicSharedMemorySize, SMEM_SZ);
        attr_set = true;
    }

    k_prep<<<16, 256>>>(W, a_self, a_neigh);
    k_fused<<<2048 + BB * NN / 16, 256>>>(A, X, W);
    dim3 grid2(NN / TIx, BB);
    k_attn<<<grid2, THR2, SMEM_SZ>>>(bias, out);
}

// round 12
// speedup vs baseline: 1.1866x; 1.0635x over previous
#include <cuda_runtime.h>
#include <cuda_fp16.h>
#include <cstdint>
#include <math.h>

// ---------------- problem constants ----------------
#define BB 8
#define NN 2048
#define FF 64
#define FHD 64
#define HH 4

#define TIx 128           // rows per CTA
#define TJx 64            // j per tile
#define NJT (NN / TJx)    // 32 j-tiles
#define THR2 512          // k_attn threads (16 warps)

#define ONES2 0x3C003C00u // half2(1.0, 1.0)

// ---------------- scratch ----------------
__device__ __half g_feats16[(size_t)BB * HH * NN * FHD]; // [b][h][n][o] fp16
__device__ float2 g_EG[BB * HH * NN];   // (exp(ss), exp(0.2 ss)) fp32
__device__ __half g_F16[BB * HH * NN];  // exp(sn) half
__device__ __half g_H16[BB * HH * NN];  // exp(0.2 sn) half
__device__ float  g_wa[2 * HH * FF];    // [which][h][f]
__device__ unsigned long long g_Abits[(size_t)BB * 32 * NN]; // [b][jt][i] 4MB

// ---------------- helpers ----------------
__device__ __forceinline__ uint32_t smem_u32(const void* p) {
    uint32_t a;
    asm("{ .reg .u64 t; cvta.to.shared.u64 t, %1; cvt.u32.u64 %0, t; }" : "=r"(a) : "l"(p));
    return a;
}
#define CP_ASYNC16(dst, src) \
    asm volatile("cp.async.cg.shared.global [%0], [%1], 16;" :: "r"(dst), "l"(src) : "memory")
#define CP_COMMIT() asm volatile("cp.async.commit_group;" ::: "memory")
#define CP_WAIT(n)  asm volatile("cp.async.wait_group %0;" :: "n"(n) : "memory")

__device__ __forceinline__ void ldmx4t(uint32_t* r, uint32_t addr) {
    asm volatile("ldmatrix.sync.aligned.m8n8.x4.trans.shared.b16 {%0,%1,%2,%3}, [%4];"
                 : "=r"(r[0]), "=r"(r[1]), "=r"(r[2]), "=r"(r[3]) : "r"(addr));
}
__device__ __forceinline__ void mma16816(float* c, const uint32_t* a, uint32_t b0, uint32_t b1) {
    asm volatile(
        "mma.sync.aligned.m16n8k16.row.col.f32.f16.f16.f32 "
        "{%0,%1,%2,%3},{%4,%5,%6,%7},{%8,%9},{%0,%1,%2,%3};"
        : "+f"(c[0]), "+f"(c[1]), "+f"(c[2]), "+f"(c[3])
        : "r"(a[0]), "r"(a[1]), "r"(a[2]), "r"(a[3]), "r"(b0), "r"(b1));
}
__device__ __forceinline__ uint32_t h2bits(__half2 v) {
    return *reinterpret_cast<uint32_t*>(&v);
}
__device__ __forceinline__ __half2 bits2h(uint32_t v) {
    return *reinterpret_cast<__half2*>(&v);
}

// ---------------- smem layout per stage (bytes) ----------------
#define OFF_V   0
#define OFF_F   36864
#define OFF_H   37376
#define OFF_M   37888
#define STGSZ   38912
#define NSTG    5
#define SMEM_SZ (NSTG * STGSZ)   // 194560/CTA -> 1 CTA/SM, deep ring

// ==================== Kernel 0: wa = W . a ====================
__global__ __launch_bounds__(256) void k_prep(
    const float* __restrict__ W, const float* __restrict__ a_self,
    const float* __restrict__ a_neigh) {
    const int lane = threadIdx.x & 31, wid = threadIdx.x >> 5;
    const int base = blockIdx.x * 32 + wid * 4;
#pragma unroll
    for (int u = 0; u < 4; ++u) {
        int idx = base + u;
        int which = idx >> 8, hf = idx & 255, h = hf >> 6;
        const float* ap = (which ? a_neigh : a_self) + h * 64;
        const float* wrow = W + (size_t)hf * 64;
        float s = wrow[lane] * ap[lane] + wrow[lane + 32] * ap[lane + 32];
#pragma unroll
        for (int d = 16; d > 0; d >>= 1) s += __shfl_xor_sync(0xffffffffu, s, d);
        if (lane == 0) g_wa[idx] = s;
    }
}

// ==================== Fused kernel: interleaved A-pack + feats ====================
// blockIdx.x % 3 in {0,1} -> pack (2048 blocks), == 2 -> feats (1024 blocks)
__global__ __launch_bounds__(256) void k_fused(
    const float* __restrict__ A, const float* __restrict__ X,
    const float* __restrict__ W) {
    const int t = threadIdx.x;
    const int role = blockIdx.x % 3;

    if (role < 2) {
        // ---------------- pack A into bitmasks (float4 + shfl nibble tree) ----------------
        __shared__ uint32_t Wd32[8][64];
        const int pid = (blockIdx.x / 3) * 2 + role;      // 0..2047
        const int b = pid >> 8, i0 = (pid & 255) * 8;
        const int lane = t & 31, wid = t >> 5;
        const float4* row = reinterpret_cast<const float4*>(
            A + ((size_t)(b * NN + i0 + wid)) * NN);
#pragma unroll
        for (int gch = 0; gch < 2; ++gch) {
            float4 v[8];
#pragma unroll
            for (int u = 0; u < 8; ++u)
                v[u] = row[(gch * 8 + u) * 32 + lane];
#pragma unroll
            for (int u = 0; u < 8; ++u) {
                uint32_t nib = (uint32_t)(v[u].x != 0.f)
                             | ((uint32_t)(v[u].y != 0.f) << 1)
                             | ((uint32_t)(v[u].z != 0.f) << 2)
                             | ((uint32_t)(v[u].w != 0.f) << 3);
                nib |= __shfl_down_sync(0xffffffffu, nib, 1) << 4;
                nib |= __shfl_down_sync(0xffffffffu, nib, 2) << 8;
                nib |= __shfl_down_sync(0xffffffffu, nib, 4) << 16;
                if ((lane & 7) == 0)
                    Wd32[wid][(gch * 8 + u) * 4 + (lane >> 3)] = nib;
            }
        }
        __syncthreads();
        int jt = t >> 3, rl = t & 7;
        unsigned long long m = (unsigned long long)Wd32[rl][jt * 2]
                             | ((unsigned long long)Wd32[rl][jt * 2 + 1] << 32);
        g_Abits[((size_t)(b * 32 + jt)) * NN + i0 + rl] = m;
    } else {
        // ---------------- feats (fp16) + E/G (fp32) + F/H (half) ----------------
        const int ROWS = 16;
        int bi = blockIdx.x / 3;                          // 0..1023
        int b  = bi >> 7;
        int n0 = (bi & 127) * ROWS;
        int h = t >> 6, o = t & 63;

        __shared__ float X_s[ROWS * 64];
        __shared__ __half F_s[ROWS][256];

        for (int idx = t; idx < ROWS * 64; idx += 256)
            X_s[idx] = X[(size_t)(b * NN + n0 + (idx >> 6)) * FF + (idx & 63)];

        float w_reg[64];
#pragma unroll
        for (int f = 0; f < 64; ++f) w_reg[f] = W[(h * 64 + f) * 64 + o];
        __syncthreads();

#pragma unroll
        for (int r = 0; r < ROWS; ++r) {
            float acc = 0.f;
#pragma unroll
            for (int f = 0; f < 64; ++f) acc += X_s[r * 64 + f] * w_reg[f];
            F_s[r][h * 64 + o] = __float2half(acc);
        }

        if (t < 128) {
            int r = t >> 3, hh = (t >> 1) & 3, wh = t & 1;
            const float* wap = g_wa + wh * 256 + hh * 64;
            float s = 0.f;
#pragma unroll
            for (int f = 0; f < 64; ++f) s += X_s[r * 64 + f] * wap[f];
            size_t idx = (size_t)(b * HH + hh) * NN + n0 + r;
            if (wh) {
                g_F16[idx] = __float2half_rn(__expf(s));
                g_H16[idx] = __float2half_rn(__expf(0.2f * s));
            } else {
                g_EG[idx] = make_float2(__expf(s), __expf(0.2f * s));
            }
        }
        __syncthreads();

#pragma unroll
        for (int k = 0; k < 2; ++k) {
            int e = t + k * 256;
            int r = e >> 5, c = (e & 31) * 8;
            int hh = c >> 6, o0 = c & 63;
            uint4 v = *reinterpret_cast<const uint4*>(&F_s[r][c]);
            *reinterpret_cast<uint4*>(
                &g_feats16[((size_t)(b * HH + hh) * NN + n0 + r) * FHD + o0]) = v;
        }
    }
}

// ==================== Kernel 2: flash-GAT (TIx=128, 5-stage ring) ====================
extern __shared__ char smem[];

__global__ __launch_bounds__(THR2, 1) void k_attn(
    const float* __restrict__ bias, float* __restrict__ out) {
    const int b  = blockIdx.y;
    const int i0 = blockIdx.x * TIx;
    const int t = threadIdx.x, lane = t & 31, wid = t >> 5;
    const int h = wid >> 2;            // head (4 warps per head)
    const int rbase = (wid & 3) * 32;  // warp owns 32 rows of 128
    const int g = lane >> 2;           // frag row group 0..7
    const int q = lane & 3;            // frag col group 0..3
    const uint32_t sb = smem_u32(smem);

    __shared__ uint32_t lutS[4];
    if (t < 4) {
        const uint32_t LUTC[4] = {0x00000000u, 0x00003C00u, 0x3C000000u, 0x3C003C00u};
        lutS[t] = LUTC[t];
    }

    auto issue_tile = [&](int jt, int stg) {
        if (jt < NJT) {
            const uint32_t base = sb + stg * STGSZ;
            const int j0 = jt * TJx;
#pragma unroll
            for (int k = 0; k < 4; ++k) {        // V: 4x64x64 half = 2048 uint4
                int e = t + k * THR2;
                int hh = e >> 9, j = (e >> 3) & 63, o8 = e & 7;
                CP_ASYNC16(base + OFF_V + hh * 9216 + j * 144 + o8 * 16,
                           &g_feats16[((size_t)(b * HH + hh) * NN + j0 + j) * FHD + o8 * 8]);
            }
            if (t < 32) {                        // F: 4x64 half
                int hh = t >> 3, jj = (t & 7) * 8;
                CP_ASYNC16(base + OFF_F + hh * 128 + jj * 2,
                           &g_F16[(size_t)(b * HH + hh) * NN + j0 + jj]);
            } else if (t < 64) {                 // H: 4x64 half
                int t2 = t - 32;
                int hh = t2 >> 3, jj = (t2 & 7) * 8;
                CP_ASYNC16(base + OFF_H + hh * 128 + jj * 2,
                           &g_H16[(size_t)(b * HH + hh) * NN + j0 + jj]);
            } else if (t < 128) {                // masks: 128 uint64 (1024B)
                int idx = t - 64;
                CP_ASYNC16(base + OFF_M + idx * 16,
                           &g_Abits[((size_t)(b * 32 + jt)) * NN + i0 + idx * 2]);
            }
        }
        CP_COMMIT();   // empty group when jt >= NJT keeps CP_WAIT count constant
    };

    // per-thread row constants as half2 duplicates (loop-invariant)
    __half2 E2d[2][2], G2d[2][2];
#pragma unroll
    for (int m = 0; m < 2; ++m)
#pragma unroll
        for (int hi = 0; hi < 2; ++hi) {
            float2 eg = g_EG[(size_t)(b * HH + h) * NN + i0 + rbase + m * 16 + g + hi * 8];
            E2d[m][hi] = __half2half2(__float2half_rn(eg.x));
            G2d[m][hi] = __half2half2(__float2half_rn(eg.y));
        }

    float acc[2][8][4];
#pragma unroll
    for (int m = 0; m < 2; ++m)
#pragma unroll
        for (int n = 0; n < 8; ++n)
#pragma unroll
            for (int c = 0; c < 4; ++c) acc[m][n][c] = 0.f;

    float acc_s[2][4];                 // row-sum accumulators (P @ ones)
#pragma unroll
    for (int m = 0; m < 2; ++m)
#pragma unroll
        for (int c = 0; c < 4; ++c) acc_s[m][c] = 0.f;

    issue_tile(0, 0);
    issue_tile(1, 1);
    issue_tile(2, 2);
    issue_tile(3, 3);

    const int rowlane = lane & 15, colsel = lane >> 4;

#pragma unroll 1
    for (int jt = 0; jt < NJT; ++jt) {
        const int stg = jt % NSTG;
        CP_WAIT(3);                      // stage jt complete (constant count)
        __syncthreads();
        issue_tile(jt + 4, (jt + 4) % NSTG);

        const char* sbase = smem + stg * STGSZ;
        const __half2* Fsh = (const __half2*)(sbase + OFF_F) + h * 32;
        const __half2* Hsh = (const __half2*)(sbase + OFF_H) + h * 32;
        const unsigned long long* Ms = (const unsigned long long*)(sbase + OFF_M);
        const uint32_t sbVh = sb + stg * STGSZ + OFF_V + h * 9216;

        // per-thread row masks, pre-shifted by q*2
        unsigned long long msk[2][2];
#pragma unroll
        for (int m = 0; m < 2; ++m)
#pragma unroll
            for (int hi = 0; hi < 2; ++hi)
                msk[m][hi] = Ms[rbase + m * 16 + g + hi * 8] >> (q * 2);

        // ---- build P in mma A-frag layout (half2 SIMD, bitmask gating) ----
        uint32_t afr[2][4][4];
#pragma unroll
        for (int k = 0; k < 4; ++k) {
            const int jc = k * 16 + q * 2;
            __half2 F2a = Fsh[jc >> 1], F2b = Fsh[(jc >> 1) + 4];
            __half2 H2a = Hsh[jc >> 1], H2b = Hsh[(jc >> 1) + 4];
#pragma unroll
            for (int m = 0; m < 2; ++m) {
                uint32_t slo0 = (uint32_t)(msk[m][0] >> (k * 16)) & 3u;
                uint32_t shi0 = (uint32_t)(msk[m][1] >> (k * 16)) & 3u;
                uint32_t slo8 = (uint32_t)(msk[m][0] >> (k * 16 + 8)) & 3u;
                uint32_t shi8 = (uint32_t)(msk[m][1] >> (k * 16 + 8)) & 3u;

                __half2 El = E2d[m][0], Gl = G2d[m][0];
                __half2 Eh = E2d[m][1], Gh = G2d[m][1];

                afr[m][k][0] = h2bits(__hmul2(
                    __hmax2(__hmul2(El, F2a), __hmul2(Gl, H2a)), bits2h(lutS[slo0])));
                afr[m][k][1] = h2bits(__hmul2(
                    __hmax2(__hmul2(Eh, F2a), __hmul2(Gh, H2a)), bits2h(lutS[shi0])));
                afr[m][k][2] = h2bits(__hmul2(
                    __hmax2(__hmul2(El, F2b), __hmul2(Gl, H2b)), bits2h(lutS[slo8])));
                afr[m][k][3] = h2bits(__hmul2(
                    __hmax2(__hmul2(Eh, F2b), __hmul2(Gh, H2b)), bits2h(lutS[shi8])));
            }
        }

        // ---- P @ V via HMMA, plus P @ ones for the denominator ----
#pragma unroll
        for (int n = 0; n < 4; ++n) {
#pragma unroll
            for (int k = 0; k < 4; ++k) {
                uint32_t bfr[4];
                ldmx4t(bfr, sbVh + (k * 16 + rowlane) * 144 + (n * 16 + colsel * 8) * 2);
#pragma unroll
                for (int m = 0; m < 2; ++m) {
                    mma16816(acc[m][2 * n],     afr[m][k], bfr[0], bfr[1]);
                    mma16816(acc[m][2 * n + 1], afr[m][k], bfr[2], bfr[3]);
                }
            }
        }
#pragma unroll
        for (int k = 0; k < 4; ++k)
#pragma unroll
            for (int m = 0; m < 2; ++m)
                mma16816(acc_s[m], afr[m][k], ONES2, ONES2);
        // no end-of-loop barrier: ring stages jt+4 never alias stages in use
    }

    // ---- denominators: every lane already holds full row sums ----
    float inv[2][2];
#pragma unroll
    for (int m = 0; m < 2; ++m) {
        inv[m][0] = 1.f / acc_s[m][0];   // row rlo
        inv[m][1] = 1.f / acc_s[m][2];   // row rhi
    }

    // ---- epilogue: normalize + bias + relu ----
#pragma unroll
    for (int n = 0; n < 8; ++n) {
        const int col = h * 64 + n * 8 + q * 2;
        float2 bv = *reinterpret_cast<const float2*>(&bias[col]);
#pragma unroll
        for (int m = 0; m < 2; ++m) {
            const int rlo = i0 + rbase + m * 16 + g;
            float2 lo, hi2;
            lo.x  = fmaxf(acc[m][n][0] * inv[m][0] + bv.x, 0.f);
            lo.y  = fmaxf(acc[m][n][1] * inv[m][0] + bv.y, 0.f);
            hi2.x = fmaxf(acc[m][n][2] * inv[m][1] + bv.x, 0.f);
            hi2.y = fmaxf(acc[m][n][3] * inv[m][1] + bv.y, 0.f);
            *reinterpret_cast<float2*>(&out[((size_t)(b * NN + rlo)) * 256 + col]) = lo;
            *reinterpret_cast<float2*>(&out[((size_t)(b * NN + rlo + 8)) * 256 + col]) = hi2;
        }
    }
}

// ==================== launch ====================
extern "C" void kernel_launch(void* const* d_in, const int* in_sizes, int n_in,
                              void* d_out, int out_size) {
    const float* X       = (const float*)d_in[0];
    const float* A       = (const float*)d_in[1];
    const float* W       = (const float*)d_in[2];
    const float* bias    = (const float*)d_in[3];
    const float* a_self  = (const float*)d_in[4];
    const float* a_neigh = (const float*)d_in[5];
    float* out = (float*)d_out;

    static bool attr_set = false;
    if (!attr_set) {
        cudaFuncSetAttribute(k_attn, cudaFuncAttributeMaxDynamicSharedMemorySize, SMEM_SZ);
        attr_set = true;
    }

    k_prep<<<16, 256>>>(W, a_self, a_neigh);
    k_fused<<<3072, 256>>>(A, X, W);
    dim3 grid2(NN / TIx, BB);
    k_attn<<<grid2, THR2, SMEM_SZ>>>(bias, out);
}